// round 17
// baseline (speedup 1.0000x reference)
#include <cuda_runtime.h>
#include <cuda_fp16.h>
#include <cstdint>

#define SEQ   4096
#define HID   2048
#define NH    16
#define NKV   8
#define HD    128
#define QDIM  (NH*HD)    // 2048
#define KVDIM (NKV*HD)   // 1024
#define KDIM  2048
#define KC    (KDIM/64)  // 32
#define QKVN  4096
#define QSCALE (0.08838834764831845f * 1.4426950408889634f)

// fp32 intermediates
__device__ float g_qkv[(size_t)SEQ * QKVN];
__device__ float g_attn[(size_t)SEQ * QDIM];

// fp16 flash operands
__device__ __half g_qh[SEQ * QDIM];
__device__ __half g_kh[SEQ * KVDIM];
__device__ __half g_vh[SEQ * KVDIM];

// int8 2-term packed operands + per-row scales
__device__ uint8_t g_pa[(size_t)SEQ * KDIM * 2];
__device__ uint8_t g_pw[(size_t)QKVN * KDIM * 2];
__device__ uint8_t g_pwo[(size_t)HID * KDIM * 2];
__device__ float g_sa[SEQ];
__device__ float g_sw[QKVN], g_swo[HID];

__device__ __forceinline__ void mma_i8(int* d,
    const uint32_t* a, uint32_t b0, uint32_t b1)
{
    asm volatile(
        "mma.sync.aligned.m16n8k32.row.col.s32.s8.s8.s32 "
        "{%0,%1,%2,%3}, {%4,%5,%6,%7}, {%8,%9}, {%0,%1,%2,%3};\n"
        : "+r"(d[0]), "+r"(d[1]), "+r"(d[2]), "+r"(d[3])
        : "r"(a[0]), "r"(a[1]), "r"(a[2]), "r"(a[3]), "r"(b0), "r"(b1));
}
__device__ __forceinline__ void mma_f16(float* d,
    const uint32_t* a, uint32_t b0, uint32_t b1)
{
    asm volatile(
        "mma.sync.aligned.m16n8k16.row.col.f32.f16.f16.f32 "
        "{%0,%1,%2,%3}, {%4,%5,%6,%7}, {%8,%9}, {%0,%1,%2,%3};\n"
        : "+f"(d[0]), "+f"(d[1]), "+f"(d[2]), "+f"(d[3])
        : "r"(a[0]), "r"(a[1]), "r"(a[2]), "r"(a[3]), "r"(b0), "r"(b1));
}
__device__ __forceinline__ void ldsm4(uint32_t* r, uint32_t addr) {
    asm volatile("ldmatrix.sync.aligned.m8n8.x4.shared.b16 {%0,%1,%2,%3}, [%4];"
                 : "=r"(r[0]), "=r"(r[1]), "=r"(r[2]), "=r"(r[3]) : "r"(addr));
}
__device__ __forceinline__ void ldsm4t(uint32_t* r, uint32_t addr) {
    asm volatile("ldmatrix.sync.aligned.m8n8.x4.trans.shared.b16 {%0,%1,%2,%3}, [%4];"
                 : "=r"(r[0]), "=r"(r[1]), "=r"(r[2]), "=r"(r[3]) : "r"(addr));
}
__device__ __forceinline__ uint32_t smem_u32(const void* p) {
    uint32_t a;
    asm("{ .reg .u64 t; cvta.to.shared.u64 t, %1; cvt.u32.u64 %0, t; }" : "=r"(a) : "l"(p));
    return a;
}
__device__ __forceinline__ void cp16(uint32_t d, const void* g) {
    asm volatile("cp.async.cg.shared.global [%0], [%1], 16;" :: "r"(d), "l"(g));
}
#define CP_COMMIT() asm volatile("cp.async.commit_group;")
#define CP_WAIT2()  asm volatile("cp.async.wait_group 2;")
#define CP_WAIT1()  asm volatile("cp.async.wait_group 1;")

__device__ __forceinline__ uint32_t exp2h2(float a, float b) {
    __half2 h = __floats2half2_rn(a, b);
    uint32_t x = *(uint32_t*)&h, r;
    asm("ex2.approx.f16x2 %0, %1;" : "=r"(r) : "r"(x));
    return r;
}
__device__ __forceinline__ float exp2s(float x) {
    float r; asm("ex2.approx.f32 %0, %1;" : "=f"(r) : "f"(x)); return r;
}
__device__ __forceinline__ uint32_t pk2(float lo, float hi) {
    __half2 t = __floats2half2_rn(lo, hi);
    return *(uint32_t*)&t;
}

// ===========================================================================
// pack_row (unchanged, passing)
// ===========================================================================
__device__ __forceinline__ void pack_row(const float* __restrict__ src,
                                         uint8_t* __restrict__ dst,
                                         float* __restrict__ scl,
                                         int row, int lane)
{
    const float* s = src + (size_t)row * KDIM;

    float4 v[16];
    float mx = 0.f;
#pragma unroll
    for (int j = 0; j < 16; j++) {
        v[j] = *(const float4*)(s + lane * 4 + j * 128);
        mx = fmaxf(mx, fmaxf(fmaxf(fabsf(v[j].x), fabsf(v[j].y)),
                             fmaxf(fabsf(v[j].z), fabsf(v[j].w))));
    }
#pragma unroll
    for (int o = 16; o; o >>= 1) mx = fmaxf(mx, __shfl_xor_sync(0xffffffffu, mx, o));

    const float s1   = mx * (1.f / 127.f);
    const float inv1 = mx > 0.f ? 127.f / mx : 0.f;
    const float inv2 = inv1 * 128.f;
    if (lane == 0) scl[row] = s1;

    const int rt = row >> 7, rr = row & 127, sw = rr & 7;
    uint8_t* tbase0 = dst + ((size_t)rt * KC) * 16384 + rr * 128;

#pragma unroll
    for (int j = 0; j < 16; j++) {
        int k = lane * 4 + j * 128;
        int c = k >> 6, w16 = (k >> 4) & 3, bin = k & 15;
        float4 x = v[j];
        int q0 = __float2int_rn(x.x * inv1), q1 = __float2int_rn(x.y * inv1);
        int q2 = __float2int_rn(x.z * inv1), q3 = __float2int_rn(x.w * inv1);
        int r0 = __float2int_rn((x.x - q0 * s1) * inv2);
        int r1 = __float2int_rn((x.y - q1 * s1) * inv2);
        int r2 = __float2int_rn((x.z - q2 * s1) * inv2);
        int r3 = __float2int_rn((x.w - q3 * s1) * inv2);
        uint8_t* tb = tbase0 + c * 16384;
        *(char4*)(tb + (((w16     ^ sw) << 4) + bin)) =
            make_char4((char)q0, (char)q1, (char)q2, (char)q3);
        *(char4*)(tb + ((((w16+4) ^ sw) << 4) + bin)) =
            make_char4((char)r0, (char)r1, (char)r2, (char)r3);
    }
}

__global__ __launch_bounds__(256)
void pack_quant(const float* __restrict__ src, uint8_t* __restrict__ dst,
                float* __restrict__ scl)
{
    const int warp = threadIdx.x >> 5, lane = threadIdx.x & 31;
    pack_row(src, dst, scl, blockIdx.x * 8 + warp, lane);
}

__global__ __launch_bounds__(256)
void pack_all(const float* __restrict__ hid,
              const float* __restrict__ wq, const float* __restrict__ wk,
              const float* __restrict__ wv, const float* __restrict__ wo,
              uint8_t* __restrict__ pa, uint8_t* __restrict__ pw,
              uint8_t* __restrict__ pwo,
              float* __restrict__ sa, float* __restrict__ sw,
              float* __restrict__ swo)
{
    const int warp = threadIdx.x >> 5, lane = threadIdx.x & 31;
    const int gr = blockIdx.x * 8 + warp;

    const float* src; uint8_t* dst; float* scl; int row;
    if (gr < 4096)      { src = hid; dst = pa;                            scl = sa;        row = gr; }
    else if (gr < 6144) { src = wq;  dst = pw;                            scl = sw;        row = gr - 4096; }
    else if (gr < 7168) { src = wk;  dst = pw + (size_t)2048 * KDIM * 2;  scl = sw + 2048; row = gr - 6144; }
    else if (gr < 8192) { src = wv;  dst = pw + (size_t)3072 * KDIM * 2;  scl = sw + 3072; row = gr - 7168; }
    else                { src = wo;  dst = pwo;                           scl = swo;       row = gr - 8192; }
    pack_row(src, dst, scl, row, lane);
}

// ===========================================================================
// gemm_i8: 3-term int8 mma, 128x128 tile, FOUR-stage pipeline (128KB smem),
// single sync per chunk, prefetch distance 3, wait_group 2.
// ===========================================================================
__global__ __launch_bounds__(256)
void gemm_i8(const uint8_t* __restrict__ Ap, const uint8_t* __restrict__ Bp,
             const float* __restrict__ sA, const float* __restrict__ sB,
             float* __restrict__ C, int N, __half* __restrict__ Vh)
{
    extern __shared__ uint8_t smi[];
    const uint32_t sb0 = smem_u32(smi);
    const int tid = threadIdx.x, lane = tid & 31, warp = tid >> 5;
    const int wm = warp >> 2, wn = warp & 3;
    const int bn = blockIdx.x, bm = blockIdx.y;

    const uint8_t* Asrc = Ap + (size_t)bm * KC * 16384 + tid * 16;
    const uint8_t* Bsrc = Bp + (size_t)bn * KC * 16384 + tid * 16;

    int acc1[4][4][4] = {}, acc2[4][4][4] = {};

    const int arow = wm * 64 + (lane & 7) + ((lane >> 3) & 1) * 8;
    const int akh  = lane >> 4;
    const int aw   = arow & 7;
    const int brow = wn * 32 + (lane & 7) + (lane >> 4) * 8;
    const int bkh  = (lane >> 3) & 1;
    const int bw   = brow & 7;

#pragma unroll
    for (int pre = 0; pre < 3; pre++) {
        uint32_t d = sb0 + pre * 32768 + tid * 16;
#pragma unroll
        for (int i = 0; i < 4; i++) cp16(d + i * 4096,         Asrc + (size_t)pre * 16384 + i * 4096);
#pragma unroll
        for (int i = 0; i < 4; i++) cp16(d + 16384 + i * 4096, Bsrc + (size_t)pre * 16384 + i * 4096);
        CP_COMMIT();
    }

    for (int kc = 0; kc < KC; kc++) {
        CP_WAIT2();
        __syncthreads();
        if (kc + 3 < KC) {
            int st3 = (kc + 3) & 3;
            uint32_t d = sb0 + st3 * 32768 + tid * 16;
#pragma unroll
            for (int i = 0; i < 4; i++) cp16(d + i * 4096,         Asrc + (size_t)(kc + 3) * 16384 + i * 4096);
#pragma unroll
            for (int i = 0; i < 4; i++) cp16(d + 16384 + i * 4096, Bsrc + (size_t)(kc + 3) * 16384 + i * 4096);
        }
        CP_COMMIT();

        const uint32_t stA = sb0 + (kc & 3) * 32768, stB = stA + 16384;

#pragma unroll
        for (int s = 0; s < 2; s++) {
            uint32_t a1f[4][4], a2f[4][4];
            const int ga = 2 * s + akh;
#pragma unroll
            for (int mi = 0; mi < 4; mi++) {
                uint32_t ad = stA + (uint32_t)(arow + mi * 16) * 128;
                ldsm4(a1f[mi], ad + (uint32_t)(((ga     ^ aw) << 4)));
                ldsm4(a2f[mi], ad + (uint32_t)((((ga+4) ^ aw) << 4)));
            }
            const int gb = 2 * s + bkh;
#pragma unroll
            for (int nj = 0; nj < 2; nj++) {
                uint32_t bd = stB + (uint32_t)(brow + nj * 16) * 128;
                uint32_t b1f[4], b2f[4];
                ldsm4(b1f, bd + (uint32_t)(((gb     ^ bw) << 4)));
                ldsm4(b2f, bd + (uint32_t)((((gb+4) ^ bw) << 4)));
#pragma unroll
                for (int mi = 0; mi < 4; mi++) {
                    mma_i8(acc1[mi][2*nj],   a1f[mi], b1f[0], b1f[1]);
                    mma_i8(acc1[mi][2*nj+1], a1f[mi], b1f[2], b1f[3]);
                    mma_i8(acc2[mi][2*nj],   a1f[mi], b2f[0], b2f[1]);
                    mma_i8(acc2[mi][2*nj+1], a1f[mi], b2f[2], b2f[3]);
                    mma_i8(acc2[mi][2*nj],   a2f[mi], b1f[0], b1f[1]);
                    mma_i8(acc2[mi][2*nj+1], a2f[mi], b1f[2], b1f[3]);
                }
            }
        }
    }

    const int u = lane >> 2, qq = (lane & 3) * 2;
    const float k2 = 0.0078125f;
    const bool isv = (Vh != nullptr) && (bn >= 24);
#pragma unroll
    for (int mi = 0; mi < 4; mi++) {
        int r0 = bm * 128 + wm * 64 + mi * 16 + u;
        float sa0 = sA[r0], sa1 = sA[r0 + 8];
#pragma unroll
        for (int nt = 0; nt < 4; nt++) {
            int c0 = bn * 128 + wn * 32 + nt * 8 + qq;
            float sb0v = sB[c0], sb1v = sB[c0 + 1];
            float d0 = ((float)acc1[mi][nt][0] + (float)acc2[mi][nt][0] * k2) * sa0 * sb0v;
            float d1 = ((float)acc1[mi][nt][1] + (float)acc2[mi][nt][1] * k2) * sa0 * sb1v;
            float d2 = ((float)acc1[mi][nt][2] + (float)acc2[mi][nt][2] * k2) * sa1 * sb0v;
            float d3 = ((float)acc1[mi][nt][3] + (float)acc2[mi][nt][3] * k2) * sa1 * sb1v;
            if (isv) {
                int vc = c0 - 3072;
                *(uint32_t*)(Vh + (size_t)r0 * KVDIM + vc)       = pk2(d0, d1);
                *(uint32_t*)(Vh + (size_t)(r0 + 8) * KVDIM + vc) = pk2(d2, d3);
            } else {
                *(float2*)(C + (size_t)r0 * N + c0)       = make_float2(d0, d1);
                *(float2*)(C + (size_t)(r0 + 8) * N + c0) = make_float2(d2, d3);
            }
        }
    }
}

// ===========================================================================
// norm_rope_cvt (unchanged, passing)
// ===========================================================================
__global__ __launch_bounds__(256)
void norm_rope_cvt(const float* __restrict__ qkv, __half* __restrict__ qo,
                   __half* __restrict__ ko,
                   const float* __restrict__ cs, const float* __restrict__ sn,
                   const float* __restrict__ qw, const float* __restrict__ kw)
{
    const int s = blockIdx.x, y = blockIdx.y;
    const int warp = threadIdx.x >> 5, lane = threadIdx.x & 31;

    const bool isq = y < 2;
    const int hh = isq ? (y * 8 + warp) : warp;
    const float* w = isq ? qw : kw;
    const float scale = isq ? (float)QSCALE : 1.0f;
    const int d0 = lane * 4;

    float4 x = *(const float4*)(qkv + (size_t)s * QKVN + (isq ? 0 : 2048) + hh * HD + d0);
    float ss = x.x * x.x + x.y * x.y + x.z * x.z + x.w * x.w;
#pragma unroll
    for (int o = 16; o; o >>= 1) ss += __shfl_xor_sync(0xffffffffu, ss, o);
    float r = rsqrtf(ss * (1.0f / 128.0f) + 1e-6f);

    float4 wv = *(const float4*)(w + d0);
    float xn0 = x.x * r * wv.x, xn1 = x.y * r * wv.y;
    float xn2 = x.z * r * wv.z, xn3 = x.w * r * wv.w;

    float p0 = __shfl_xor_sync(0xffffffffu, xn0, 16);
    float p1 = __shfl_xor_sync(0xffffffffu, xn1, 16);
    float p2 = __shfl_xor_sync(0xffffffffu, xn2, 16);
    float p3 = __shfl_xor_sync(0xffffffffu, xn3, 16);
    float sg = (lane < 16) ? -1.0f : 1.0f;

    float4 c4 = *(const float4*)(cs + s * HD + d0);
    float4 s4 = *(const float4*)(sn + s * HD + d0);
    float o0 = (xn0 * c4.x + sg * p0 * s4.x) * scale;
    float o1 = (xn1 * c4.y + sg * p1 * s4.y) * scale;
    float o2 = (xn2 * c4.z + sg * p2 * s4.z) * scale;
    float o3 = (xn3 * c4.w + sg * p3 * s4.w) * scale;

    uint2 pk; pk.x = pk2(o0, o1); pk.y = pk2(o2, o3);
    if (isq) *(uint2*)(qo + (size_t)s * QDIM + hh * HD + d0) = pk;
    else     *(uint2*)(ko + (size_t)s * KVDIM + hh * HD + d0) = pk;
}

// ===========================================================================
// fp16 flash attention: 64-row Q, 4 warps, 64-key tiles, 3 stages, 2 CTA/SM.
// New: warp-vote rescale skip; l-update after PV (off critical path).
// ===========================================================================
__global__ __launch_bounds__(128, 2)
void flash_f16()
{
    extern __shared__ uint8_t smf[];
    const uint32_t sQ = smem_u32(smf);
    const uint32_t sKV0 = sQ + 16384;

    const int tid = threadIdx.x, lane = tid & 31, warp = tid >> 5;
    const int qb = gridDim.x - 1 - blockIdx.x;
    const int h = blockIdx.y, kvh = h >> 1;
    const int q2 = lane & 3, u = lane >> 2;
    const uint32_t ONES2 = 0x3C003C00u;

    const uint8_t* Kg0 = (const uint8_t*)(g_kh + (size_t)kvh * HD);
    const uint8_t* Vg0 = (const uint8_t*)(g_vh + (size_t)kvh * HD);
    const int njb = qb + 1;

    {
        const uint8_t* Qg = (const uint8_t*)(g_qh + ((size_t)(qb * 64) * NH + h) * HD);
#pragma unroll
        for (int j = 0; j < 8; j++) {
            int idx = tid + j * 128;
            int row = idx >> 4, g = idx & 15;
            cp16(sQ + row * 256 + ((g ^ (row & 7)) << 4),
                 Qg + (size_t)row * NH * HD * 2 + g * 16);
        }
        CP_COMMIT();
    }
#pragma unroll
    for (int pre = 0; pre < 2; pre++) {
        uint32_t st = sKV0 + pre * 32768;
        const uint8_t* Kg = Kg0 + (size_t)(pre * 64) * NKV * HD * 2;
        const uint8_t* Vg = Vg0 + (size_t)(pre * 64) * NKV * HD * 2;
#pragma unroll
        for (int j = 0; j < 8; j++) {
            int idx = tid + j * 128;
            int row = idx >> 4, g = idx & 15;
            uint32_t off = row * 256 + ((g ^ (row & 7)) << 4);
            size_t gsrc = (size_t)row * NKV * HD * 2 + g * 16;
            cp16(st + off, Kg + gsrc);
            cp16(st + 16384 + off, Vg + gsrc);
        }
        CP_COMMIT();
    }

    CP_WAIT2();
    __syncthreads();

    uint32_t qf[8][4];
    {
        int row = warp * 16 + (lane & 7) + ((lane >> 3) & 1) * 8;
        int go  = lane >> 4;
        uint32_t rb = sQ + row * 256;
        int rw = (row & 7);
#pragma unroll
        for (int ks = 0; ks < 8; ks++)
            ldsm4(qf[ks], rb + (((2 * ks + go) ^ rw) << 4));
    }

    float o[16][4];
#pragma unroll
    for (int i = 0; i < 16; i++)
#pragma unroll
        for (int r = 0; r < 4; r++) o[i][r] = 0.f;
    float m0 = -1e30f, m1 = -1e30f, l0 = 0.f, l1 = 0.f;

    const int kkey = lane & 7;
    const int kgo  = lane >> 3;
    const int vkey = (lane & 7) + ((lane >> 3) & 1) * 8;
    const int vgo  = lane >> 4;

    for (int jb = 0; jb < njb; jb++) {
        CP_WAIT1();
        __syncthreads();

        if (jb + 2 < njb) {
            uint32_t st = sKV0 + ((jb + 2) % 3) * 32768;
            const uint8_t* Kg = Kg0 + (size_t)((jb + 2) * 64) * NKV * HD * 2;
            const uint8_t* Vg = Vg0 + (size_t)((jb + 2) * 64) * NKV * HD * 2;
#pragma unroll
            for (int j = 0; j < 8; j++) {
                int idx = tid + j * 128;
                int row = idx >> 4, g = idx & 15;
                uint32_t off = row * 256 + ((g ^ (row & 7)) << 4);
                size_t gsrc = (size_t)row * NKV * HD * 2 + g * 16;
                cp16(st + off, Kg + gsrc);
                cp16(st + 16384 + off, Vg + gsrc);
            }
        }
        CP_COMMIT();

        const uint32_t sK = sKV0 + (jb % 3) * 32768, sV = sK + 16384;

        float s[8][4];
#pragma unroll
        for (int nt = 0; nt < 8; nt++)
#pragma unroll
            for (int r = 0; r < 4; r++) s[nt][r] = 0.f;

#pragma unroll
        for (int g2 = 0; g2 < 4; g2++) {
#pragma unroll
            for (int nt = 0; nt < 8; nt++) {
                int key = 8 * nt + kkey;
                uint32_t bf[4];
                ldsm4(bf, sK + key * 256 + (((4 * g2 + kgo) ^ (key & 7)) << 4));
                mma_f16(s[nt], qf[2 * g2],     bf[0], bf[1]);
                mma_f16(s[nt], qf[2 * g2 + 1], bf[2], bf[3]);
            }
        }

        if (jb == qb) {
            int r0g = qb * 64 + warp * 16 + u;
            int cb = jb * 64 + q2 * 2;
#pragma unroll
            for (int nt = 0; nt < 8; nt++) {
                int c = cb + nt * 8;
                if (c     > r0g)     s[nt][0] = -1e30f;
                if (c + 1 > r0g)     s[nt][1] = -1e30f;
                if (c     > r0g + 8) s[nt][2] = -1e30f;
                if (c + 1 > r0g + 8) s[nt][3] = -1e30f;
            }
        }

        float mx0 = -1e30f, mx1 = -1e30f;
#pragma unroll
        for (int nt = 0; nt < 8; nt++) {
            mx0 = fmaxf(mx0, fmaxf(s[nt][0], s[nt][1]));
            mx1 = fmaxf(mx1, fmaxf(s[nt][2], s[nt][3]));
        }
        mx0 = fmaxf(mx0, __shfl_xor_sync(0xffffffffu, mx0, 1));
        mx0 = fmaxf(mx0, __shfl_xor_sync(0xffffffffu, mx0, 2));
        mx1 = fmaxf(mx1, __shfl_xor_sync(0xffffffffu, mx1, 1));
        mx1 = fmaxf(mx1, __shfl_xor_sync(0xffffffffu, mx1, 2));

        // warp-vote rescale skip: exact when no row saw a new max
        if (!__all_sync(0xffffffffu, (mx0 <= m0) & (mx1 <= m1))) {
            float mn0 = fmaxf(m0, mx0), mn1 = fmaxf(m1, mx1);
            float cf0 = exp2s(m0 - mn0), cf1 = exp2s(m1 - mn1);
            m0 = mn0; m1 = mn1;
            l0 *= cf0; l1 *= cf1;
#pragma unroll
            for (int nt2 = 0; nt2 < 16; nt2++) {
                o[nt2][0] *= cf0; o[nt2][1] *= cf0;
                o[nt2][2] *= cf1; o[nt2][3] *= cf1;
            }
        }

        uint32_t pf[4][4];
#pragma unroll
        for (int kt = 0; kt < 4; kt++) {
            pf[kt][0] = exp2h2(s[2*kt][0]   - m0, s[2*kt][1]   - m0);
            pf[kt][1] = exp2h2(s[2*kt][2]   - m1, s[2*kt][3]   - m1);
            pf[kt][2] = exp2h2(s[2*kt+1][0] - m0, s[2*kt+1][1] - m0);
            pf[kt][3] = exp2h2(s[2*kt+1][2] - m1, s[2*kt+1][3] - m1);
        }

        // O += P V
#pragma unroll
        for (int ks = 0; ks < 4; ks++) {
#pragma unroll
            for (int np = 0; np < 8; np++) {
                int key = 16 * ks + vkey;
                uint32_t vf[4];
                ldsm4t(vf, sV + key * 256 + (((2 * np + vgo) ^ (key & 7)) << 4));
                mma_f16(o[2 * np],     pf[ks], vf[0], vf[1]);
                mma_f16(o[2 * np + 1], pf[ks], vf[2], vf[3]);
            }
        }

        // row sums (off the critical path, after PV)
        float rsd[4] = {0.f, 0.f, 0.f, 0.f};
#pragma unroll
        for (int kt = 0; kt < 4; kt++)
            mma_f16(rsd, pf[kt], ONES2, ONES2);
        l0 += rsd[0];
        l1 += rsd[2];
    }

    float r0i = 1.f / l0, r1i = 1.f / l1;
    int grow = qb * 64 + warp * 16 + u;
#pragma unroll
    for (int nt2 = 0; nt2 < 16; nt2++) {
        int col = h * HD + nt2 * 8 + q2 * 2;
        *(float2*)(g_attn + (size_t)grow * QDIM + col) =
            make_float2(o[nt2][0] * r0i, o[nt2][1] * r0i);
        *(float2*)(g_attn + (size_t)(grow + 8) * QDIM + col) =
            make_float2(o[nt2][2] * r1i, o[nt2][3] * r1i);
    }
}

// ===========================================================================
extern "C" void kernel_launch(void* const* d_in, const int* in_sizes, int n_in,
                              void* d_out, int out_size)
{
    const float* hid  = (const float*)d_in[0];
    const float* cosp = (const float*)d_in[1];
    const float* sinp = (const float*)d_in[2];
    const float* wq   = (const float*)d_in[3];
    const float* wk   = (const float*)d_in[4];
    const float* wv   = (const float*)d_in[5];
    const float* wo   = (const float*)d_in[6];
    const float* qw   = (const float*)d_in[7];
    const float* kw   = (const float*)d_in[8];
    float* out = (float*)d_out;

    float *qkv, *ab;
    cudaGetSymbolAddress((void**)&qkv, g_qkv);
    cudaGetSymbolAddress((void**)&ab, g_attn);
    __half *qh, *kh, *vh;
    cudaGetSymbolAddress((void**)&qh, g_qh);
    cudaGetSymbolAddress((void**)&kh, g_kh);
    cudaGetSymbolAddress((void**)&vh, g_vh);
    uint8_t *pa, *pw, *pwo;
    cudaGetSymbolAddress((void**)&pa,  g_pa);
    cudaGetSymbolAddress((void**)&pw,  g_pw);
    cudaGetSymbolAddress((void**)&pwo, g_pwo);
    float *sa, *sw, *swo;
    cudaGetSymbolAddress((void**)&sa,  g_sa);
    cudaGetSymbolAddress((void**)&sw,  g_sw);
    cudaGetSymbolAddress((void**)&swo, g_swo);

    const int GEMM_SMEM  = 131072;   // 4 stages x 32KB
    const int FLASH_SMEM = 114688;   // Q 16KB + 3 x 32KB -> 2 CTAs/SM
    cudaFuncSetAttribute(gemm_i8, cudaFuncAttributeMaxDynamicSharedMemorySize, GEMM_SMEM);
    cudaFuncSetAttribute(flash_f16, cudaFuncAttributeMaxDynamicSharedMemorySize, FLASH_SMEM);

    pack_all<<<1280, 256>>>(hid, wq, wk, wv, wo, pa, pw, pwo, sa, sw, swo);

    gemm_i8<<<dim3(QKVN / 128, SEQ / 128), 256, GEMM_SMEM>>>(pa, pw, sa, sw, qkv, QKVN, vh);

    norm_rope_cvt<<<dim3(SEQ, 3), 256>>>(qkv, qh, kh, cosp, sinp, qw, kw);

    flash_f16<<<dim3(SEQ / 64, NH), 128, FLASH_SMEM>>>();

    pack_quant<<<SEQ / 8, 256>>>(ab, pa, sa);
    gemm_i8<<<dim3(HID / 128, SEQ / 128), 256, GEMM_SMEM>>>(pa, pwo, sa, swo, out, HID, nullptr);
}